// round 1
// baseline (speedup 1.0000x reference)
#include <cuda_runtime.h>
#include <math.h>

// Problem constants
#define PB 2
#define PS 2048
#define PD 4096
#define PH 32
#define PHD 128
#define PAL 10
#define PM (PB*PS)          // 4096 rows
#define NELEM (PB*PS*PD)    // 16777216

// Scratch (device globals — no allocation APIs allowed)
__device__ float g_q[NELEM];
__device__ float g_k[NELEM];
__device__ float g_v[NELEM];
__device__ float g_o[NELEM];
__device__ float g_ak[PAL*PD];
__device__ float g_av[PAL*PD];

// ---------------------------------------------------------------------------
// SGEMM: C[M,N] = A[M,K] * B[K,N], all row-major, M=N=K multiples of 128/8.
// 128x128 block tile, BK=8, 256 threads, 8x8 per thread, register-staged
// global prefetch.
// ---------------------------------------------------------------------------
__global__ __launch_bounds__(256) void sgemm128(
    const float* __restrict__ A, const float* __restrict__ B,
    float* __restrict__ C, int M, int N, int K)
{
    __shared__ float As[8][128];
    __shared__ float Bs[8][128];

    const int tid = threadIdx.x;
    const int tc = tid & 15;        // 0..15 -> C cols
    const int tr = tid >> 4;        // 0..15 -> C rows
    const int bm = blockIdx.y * 128;
    const int bn = blockIdx.x * 128;

    const int aRow = tid >> 1;          // 0..127
    const int aCol = (tid & 1) << 2;    // 0 or 4
    const int bRow = tid >> 5;          // 0..7
    const int bCol = (tid & 31) << 2;   // 0..124

    const float* Ap = A + (size_t)(bm + aRow) * K + aCol;
    const float* Bp = B + (size_t)bRow * N + bn + bCol;

    float acc[8][8];
#pragma unroll
    for (int i = 0; i < 8; i++)
#pragma unroll
        for (int j = 0; j < 8; j++) acc[i][j] = 0.f;

    float4 a4 = *(const float4*)Ap;
    float4 b4 = *(const float4*)Bp;

    const int nk = K >> 3;
    for (int kt = 0; kt < nk; kt++) {
        // store staged tile into smem (A transposed)
        As[aCol + 0][aRow] = a4.x;
        As[aCol + 1][aRow] = a4.y;
        As[aCol + 2][aRow] = a4.z;
        As[aCol + 3][aRow] = a4.w;
        *(float4*)&Bs[bRow][bCol] = b4;
        __syncthreads();

        if (kt + 1 < nk) {
            a4 = *(const float4*)(Ap + (size_t)(kt + 1) * 8);
            b4 = *(const float4*)(Bp + (size_t)(kt + 1) * 8 * N);
        }

#pragma unroll
        for (int kk = 0; kk < 8; kk++) {
            float4 x0 = *(float4*)&As[kk][tr * 8];
            float4 x1 = *(float4*)&As[kk][tr * 8 + 4];
            float4 y0 = *(float4*)&Bs[kk][tc * 8];
            float4 y1 = *(float4*)&Bs[kk][tc * 8 + 4];
            float av_[8] = {x0.x, x0.y, x0.z, x0.w, x1.x, x1.y, x1.z, x1.w};
            float bv_[8] = {y0.x, y0.y, y0.z, y0.w, y1.x, y1.y, y1.z, y1.w};
#pragma unroll
            for (int i = 0; i < 8; i++)
#pragma unroll
                for (int j = 0; j < 8; j++)
                    acc[i][j] += av_[i] * bv_[j];
        }
        __syncthreads();
    }

    float* Cp = C + (size_t)(bm + tr * 8) * N + bn + tc * 8;
#pragma unroll
    for (int i = 0; i < 8; i++) {
        *(float4*)(Cp + (size_t)i * N) =
            make_float4(acc[i][0], acc[i][1], acc[i][2], acc[i][3]);
        *(float4*)(Cp + (size_t)i * N + 4) =
            make_float4(acc[i][4], acc[i][5], acc[i][6], acc[i][7]);
    }
}

// ---------------------------------------------------------------------------
// RoPE, in place: x shape (B,S,H,HD), pairs (2p, 2p+1).
// ---------------------------------------------------------------------------
__global__ __launch_bounds__(256) void rope_k(
    float* __restrict__ X, const float* __restrict__ Ct, const float* __restrict__ St)
{
    int i = blockIdx.x * 256 + threadIdx.x;   // over B*S*H*64 = 8388608
    if (i >= PB * PS * PH * 64) return;
    int p = i & 63;
    int h = (i >> 6) & 31;
    int s = (i >> 11) & 2047;
    int b = i >> 22;
    float c = Ct[(s << 6) + p];
    float sn = St[(s << 6) + p];
    size_t base = (((size_t)(b << 11) + s) << 12) + (h << 7) + (p << 1);
    float x0 = X[base], x1 = X[base + 1];
    X[base]     = x0 * c - x1 * sn;
    X[base + 1] = x0 * sn + x1 * c;
}

// ---------------------------------------------------------------------------
// Adapter projection: Out[AL,D] = adapter[AL,K=4096] @ W[4096,D]. Deterministic,
// no atomics. grid = D/256 blocks, 256 threads, each thread owns one n-col and
// keeps AL accumulators.
// ---------------------------------------------------------------------------
__global__ __launch_bounds__(256) void adapter_proj(
    const float* __restrict__ Ad, const float* __restrict__ W, float* __restrict__ Out)
{
    __shared__ float sAd[PAL][512];
    int n = blockIdx.x * 256 + threadIdx.x;
    float acc[PAL];
#pragma unroll
    for (int a = 0; a < PAL; a++) acc[a] = 0.f;

    for (int k0 = 0; k0 < PD; k0 += 512) {
        __syncthreads();
        for (int i = threadIdx.x; i < PAL * 512; i += 256) {
            int a = i / 512, kk = i - a * 512;
            sAd[a][kk] = Ad[a * PD + k0 + kk];
        }
        __syncthreads();
#pragma unroll 8
        for (int kk = 0; kk < 512; kk++) {
            float w = W[(size_t)(k0 + kk) * PD + n];
#pragma unroll
            for (int a = 0; a < PAL; a++) acc[a] += sAd[a][kk] * w;
        }
    }
#pragma unroll
    for (int a = 0; a < PAL; a++) Out[a * PD + n] = acc[a];
}

// ---------------------------------------------------------------------------
// Flash attention fp32 + fused gated adapter attention.
// Block: 256 threads (tx=0..15, ty=0..15), handles one (b, h, 64-query tile).
// Each thread: S-phase owns 4q x 4k of scores; PV-phase owns 4q x 8d of output.
// smem: Qs/Ks/Vs 64x132 (padded), Ps 64x68 -> 118784 B dynamic.
// ---------------------------------------------------------------------------
#define FLASH_SMEM ((3 * 64 * 132 + 64 * 68) * 4)

__global__ __launch_bounds__(256) void flashattn(
    const float* __restrict__ Q, const float* __restrict__ K,
    const float* __restrict__ V, const float* __restrict__ AK,
    const float* __restrict__ AV, const float* __restrict__ gate,
    float* __restrict__ O)
{
    extern __shared__ float sm[];
    float* Qs = sm;                 // [64][132]
    float* Ks = Qs + 64 * 132;      // [64][132]
    float* Vs = Ks + 64 * 132;      // [64][132]
    float* Ps = Vs + 64 * 132;      // [64][68]

    const int qt = blockIdx.x, h = blockIdx.y, b = blockIdx.z;
    const int tid = threadIdx.x;
    const int tx = tid & 15, ty = tid >> 4;
    const float inv_sqrt = 0.088388347648318447f;   // 1/sqrt(128)

    // Load Q tile (64 rows x 128 cols)
    const size_t baseQ = ((size_t)(b * PS) + qt * 64) * PD + h * PHD;
    for (int i = tid; i < 64 * 32; i += 256) {
        int r = i >> 5, c4 = (i & 31) << 2;
        *(float4*)&Qs[r * 132 + c4] =
            *(const float4*)(Q + baseQ + (size_t)r * PD + c4);
    }

    float m_[4], l_[4], acc[4][8];
#pragma unroll
    for (int qi = 0; qi < 4; qi++) {
        m_[qi] = -3.0e38f; l_[qi] = 0.f;
#pragma unroll
        for (int j = 0; j < 8; j++) acc[qi][j] = 0.f;
    }

    for (int kt = 0; kt <= qt; kt++) {
        __syncthreads();   // prev PV done (and Qs ready on first iter)
        const size_t baseK = ((size_t)(b * PS) + kt * 64) * PD + h * PHD;
        for (int i = tid; i < 64 * 32; i += 256) {
            int r = i >> 5, c4 = (i & 31) << 2;
            *(float4*)&Ks[r * 132 + c4] =
                *(const float4*)(K + baseK + (size_t)r * PD + c4);
            *(float4*)&Vs[r * 132 + c4] =
                *(const float4*)(V + baseK + (size_t)r * PD + c4);
        }
        __syncthreads();

        // S = Q K^T  (4q x 4k per thread)
        float s[4][4];
#pragma unroll
        for (int qi = 0; qi < 4; qi++)
#pragma unroll
            for (int kj = 0; kj < 4; kj++) s[qi][kj] = 0.f;

#pragma unroll 4
        for (int d = 0; d < 128; d += 4) {
            float4 qv[4], kv[4];
#pragma unroll
            for (int qi = 0; qi < 4; qi++)
                qv[qi] = *(float4*)&Qs[(ty * 4 + qi) * 132 + d];
#pragma unroll
            for (int kj = 0; kj < 4; kj++)
                kv[kj] = *(float4*)&Ks[(tx * 4 + kj) * 132 + d];
#pragma unroll
            for (int qi = 0; qi < 4; qi++)
#pragma unroll
                for (int kj = 0; kj < 4; kj++) {
                    s[qi][kj] += qv[qi].x * kv[kj].x;
                    s[qi][kj] += qv[qi].y * kv[kj].y;
                    s[qi][kj] += qv[qi].z * kv[kj].z;
                    s[qi][kj] += qv[qi].w * kv[kj].w;
                }
        }

        // scale + causal mask (only diagonal tile needs it)
        const int qrow0 = qt * 64 + ty * 4;
#pragma unroll
        for (int qi = 0; qi < 4; qi++)
#pragma unroll
            for (int kj = 0; kj < 4; kj++) {
                float v = s[qi][kj] * inv_sqrt;
                if (kt == qt && (kt * 64 + tx * 4 + kj) > (qrow0 + qi))
                    v = -1.0e9f;
                s[qi][kj] = v;
            }

        // online softmax per row (reduce across 16 tx lanes via xor-shfl<16)
#pragma unroll
        for (int qi = 0; qi < 4; qi++) {
            float tm = fmaxf(fmaxf(s[qi][0], s[qi][1]), fmaxf(s[qi][2], s[qi][3]));
#pragma unroll
            for (int o = 8; o >= 1; o >>= 1)
                tm = fmaxf(tm, __shfl_xor_sync(0xffffffffu, tm, o));
            float mn = fmaxf(m_[qi], tm);
            float sc = __expf(m_[qi] - mn);
            float ls = 0.f;
#pragma unroll
            for (int kj = 0; kj < 4; kj++) {
                float p = __expf(s[qi][kj] - mn);
                s[qi][kj] = p;
                ls += p;
            }
#pragma unroll
            for (int o = 8; o >= 1; o >>= 1)
                ls += __shfl_xor_sync(0xffffffffu, ls, o);
            l_[qi] = l_[qi] * sc + ls;
            m_[qi] = mn;
#pragma unroll
            for (int j = 0; j < 8; j++) acc[qi][j] *= sc;
#pragma unroll
            for (int kj = 0; kj < 4; kj++)
                Ps[(ty * 4 + qi) * 68 + tx * 4 + kj] = s[qi][kj];
        }
        __syncthreads();

        // PV: acc[4q][8d] += P[4q][k] * V[k][8d]
#pragma unroll 4
        for (int k = 0; k < 64; k++) {
            float pv0 = Ps[(ty * 4 + 0) * 68 + k];
            float pv1 = Ps[(ty * 4 + 1) * 68 + k];
            float pv2 = Ps[(ty * 4 + 2) * 68 + k];
            float pv3 = Ps[(ty * 4 + 3) * 68 + k];
            float4 v0 = *(float4*)&Vs[k * 132 + tx * 8];
            float4 v1 = *(float4*)&Vs[k * 132 + tx * 8 + 4];
            float vv[8] = {v0.x, v0.y, v0.z, v0.w, v1.x, v1.y, v1.z, v1.w};
#pragma unroll
            for (int j = 0; j < 8; j++) {
                acc[0][j] += pv0 * vv[j];
                acc[1][j] += pv1 * vv[j];
                acc[2][j] += pv2 * vv[j];
                acc[3][j] += pv3 * vv[j];
            }
        }
    }

    // normalize
#pragma unroll
    for (int qi = 0; qi < 4; qi++) {
        float inv = 1.f / l_[qi];
#pragma unroll
        for (int j = 0; j < 8; j++) acc[qi][j] *= inv;
    }

    // Fused adapter attention: gate[h] * softmax(q . ak / sqrt(HD)) @ av
    const float g = gate[h];
#pragma unroll
    for (int qi = 0; qi < 4; qi++) {
        const int row = ty * 4 + qi;
        float sa[PAL];
#pragma unroll
        for (int a = 0; a < PAL; a++) {
            float part = 0.f;
#pragma unroll
            for (int j = 0; j < 8; j++)
                part += Qs[row * 132 + tx * 8 + j] *
                        AK[a * PD + h * PHD + tx * 8 + j];
#pragma unroll
            for (int o = 8; o >= 1; o >>= 1)
                part += __shfl_xor_sync(0xffffffffu, part, o);
            sa[a] = part * inv_sqrt;
        }
        float mx = sa[0];
#pragma unroll
        for (int a = 1; a < PAL; a++) mx = fmaxf(mx, sa[a]);
        float se = 0.f;
#pragma unroll
        for (int a = 0; a < PAL; a++) { sa[a] = __expf(sa[a] - mx); se += sa[a]; }
        float gs = g / se;
#pragma unroll
        for (int j = 0; j < 8; j++) {
            float add = 0.f;
#pragma unroll
            for (int a = 0; a < PAL; a++)
                add += sa[a] * AV[a * PD + h * PHD + tx * 8 + j];
            acc[qi][j] += gs * add;
        }
    }

    // write output in (B,S,H*HD) layout
    const size_t baseO = ((size_t)(b * PS) + qt * 64) * PD + h * PHD;
#pragma unroll
    for (int qi = 0; qi < 4; qi++) {
        int row = ty * 4 + qi;
        *(float4*)(O + baseO + (size_t)row * PD + tx * 8) =
            make_float4(acc[qi][0], acc[qi][1], acc[qi][2], acc[qi][3]);
        *(float4*)(O + baseO + (size_t)row * PD + tx * 8 + 4) =
            make_float4(acc[qi][4], acc[qi][5], acc[qi][6], acc[qi][7]);
    }
}

// ---------------------------------------------------------------------------
// kernel_launch: graph-capturable sequence on default stream.
// ---------------------------------------------------------------------------
extern "C" void kernel_launch(void* const* d_in, const int* in_sizes, int n_in,
                              void* d_out, int out_size)
{
    (void)in_sizes; (void)n_in; (void)out_size;
    const float* x       = (const float*)d_in[0];
    const float* cosT    = (const float*)d_in[1];
    const float* sinT    = (const float*)d_in[2];
    // d_in[3] = mask (hardcoded causal -1e9), d_in[10] = random_init (0)
    const float* wq      = (const float*)d_in[4];
    const float* wk      = (const float*)d_in[5];
    const float* wv      = (const float*)d_in[6];
    const float* wo      = (const float*)d_in[7];
    const float* gate    = (const float*)d_in[8];
    const float* adapter = (const float*)d_in[9];
    float* out = (float*)d_out;

    float *q, *k, *v, *o, *ak, *av;
    cudaGetSymbolAddress((void**)&q,  g_q);
    cudaGetSymbolAddress((void**)&k,  g_k);
    cudaGetSymbolAddress((void**)&v,  g_v);
    cudaGetSymbolAddress((void**)&o,  g_o);
    cudaGetSymbolAddress((void**)&ak, g_ak);
    cudaGetSymbolAddress((void**)&av, g_av);

    dim3 gg(PD / 128, PM / 128);   // 32 x 32

    sgemm128<<<gg, 256>>>(x, wq, q, PM, PD, PD);
    sgemm128<<<gg, 256>>>(x, wk, k, PM, PD, PD);
    sgemm128<<<gg, 256>>>(x, wv, v, PM, PD, PD);

    adapter_proj<<<PD / 256, 256>>>(adapter, wk, ak);
    adapter_proj<<<PD / 256, 256>>>(adapter, wv, av);

    const int ropeN = PB * PS * PH * 64;
    rope_k<<<ropeN / 256, 256>>>(q, cosT, sinT);
    rope_k<<<ropeN / 256, 256>>>(k, cosT, sinT);

    cudaFuncSetAttribute(flashattn, cudaFuncAttributeMaxDynamicSharedMemorySize,
                         FLASH_SMEM);
    flashattn<<<dim3(PS / 64, PH, PB), 256, FLASH_SMEM>>>(q, k, v, ak, av, gate, o);

    sgemm128<<<gg, 256>>>(o, wo, out, PM, PD, PD);
}

// round 4
// speedup vs baseline: 1.7994x; 1.7994x over previous
#include <cuda_runtime.h>
#include <cuda_bf16.h>
#include <cstdint>
#include <math.h>

// Problem constants
#define PB 2
#define PS 2048
#define PD 4096
#define PH 32
#define PHD 128
#define PAL 10
#define PM (PB*PS)          // 4096 rows
#define NELEM (PB*PS*PD)    // 16777216

// ---------------------------------------------------------------------------
// Scratch (device globals — no allocation APIs allowed)
// ---------------------------------------------------------------------------
__device__ float g_q[NELEM];
__device__ float g_k[NELEM];
__device__ float g_v[NELEM];
__device__ float g_o[NELEM];
__device__ float g_ak[PAL*PD];
__device__ float g_av[PAL*PD];
__device__ float g_adp[8*PAL*PD];

__device__ __nv_bfloat16 g_xhi[NELEM];
__device__ __nv_bfloat16 g_xlo[NELEM];
__device__ __nv_bfloat16 g_ohi[NELEM];
__device__ __nv_bfloat16 g_olo[NELEM];
__device__ __nv_bfloat16 g_wqT_hi[PD*PD];
__device__ __nv_bfloat16 g_wqT_lo[PD*PD];
__device__ __nv_bfloat16 g_wkT_hi[PD*PD];
__device__ __nv_bfloat16 g_wkT_lo[PD*PD];
__device__ __nv_bfloat16 g_wvT_hi[PD*PD];
__device__ __nv_bfloat16 g_wvT_lo[PD*PD];
__device__ __nv_bfloat16 g_woT_hi[PD*PD];
__device__ __nv_bfloat16 g_woT_lo[PD*PD];

// ---------------------------------------------------------------------------
// Base-target PTX helpers: cp.async, ldmatrix, mma.sync (NO tcgen05 — the
// harness compiles to .target sm_103 base, which rejects all 'a' features).
// ---------------------------------------------------------------------------
__device__ __forceinline__ uint32_t smem_u32(const void* p) {
    uint32_t a;
    asm("{ .reg .u64 t; cvta.to.shared.u64 t, %1; cvt.u32.u64 %0, t; }"
        : "=r"(a) : "l"(p));
    return a;
}
__device__ __forceinline__ void cpa16(uint32_t s, const void* g) {
    asm volatile("cp.async.ca.shared.global [%0], [%1], 16;" :: "r"(s), "l"(g));
}
#define CP_COMMIT() asm volatile("cp.async.commit_group;" ::: "memory")
#define CP_WAIT1()  asm volatile("cp.async.wait_group 1;" ::: "memory")
#define CP_WAIT0()  asm volatile("cp.async.wait_group 0;" ::: "memory")

__device__ __forceinline__ void ldmA(uint32_t a, uint32_t r[4]) {
    asm volatile("ldmatrix.sync.aligned.m8n8.x4.shared.b16 {%0,%1,%2,%3}, [%4];"
        : "=r"(r[0]), "=r"(r[1]), "=r"(r[2]), "=r"(r[3]) : "r"(a));
}
__device__ __forceinline__ void ldmB(uint32_t a, uint32_t r[2]) {
    asm volatile("ldmatrix.sync.aligned.m8n8.x2.shared.b16 {%0,%1}, [%2];"
        : "=r"(r[0]), "=r"(r[1]) : "r"(a));
}
__device__ __forceinline__ void mma16816(float d[4], const uint32_t a[4],
                                         const uint32_t b[2]) {
    asm volatile(
        "mma.sync.aligned.m16n8k16.row.col.f32.bf16.bf16.f32 "
        "{%0,%1,%2,%3}, {%4,%5,%6,%7}, {%8,%9}, {%0,%1,%2,%3};"
        : "+f"(d[0]), "+f"(d[1]), "+f"(d[2]), "+f"(d[3])
        : "r"(a[0]), "r"(a[1]), "r"(a[2]), "r"(a[3]), "r"(b[0]), "r"(b[1]));
}

// ---------------------------------------------------------------------------
// bf16 split conversions
// ---------------------------------------------------------------------------
__global__ __launch_bounds__(256) void split_bf16(
    const float* __restrict__ X, __nv_bfloat16* __restrict__ Hi,
    __nv_bfloat16* __restrict__ Lo, int n4)
{
    int i = blockIdx.x * 256 + threadIdx.x;
    if (i >= n4) return;
    float4 v = *(const float4*)(X + (size_t)i * 4);
    __nv_bfloat16 h0 = __float2bfloat16(v.x);
    __nv_bfloat16 h1 = __float2bfloat16(v.y);
    __nv_bfloat16 h2 = __float2bfloat16(v.z);
    __nv_bfloat16 h3 = __float2bfloat16(v.w);
    __nv_bfloat16 l0 = __float2bfloat16(v.x - __bfloat162float(h0));
    __nv_bfloat16 l1 = __float2bfloat16(v.y - __bfloat162float(h1));
    __nv_bfloat16 l2 = __float2bfloat16(v.z - __bfloat162float(h2));
    __nv_bfloat16 l3 = __float2bfloat16(v.w - __bfloat162float(h3));
    __nv_bfloat162 hp0; hp0.x = h0; hp0.y = h1;
    __nv_bfloat162 hp1; hp1.x = h2; hp1.y = h3;
    __nv_bfloat162 lp0; lp0.x = l0; lp0.y = l1;
    __nv_bfloat162 lp1; lp1.x = l2; lp1.y = l3;
    *(__nv_bfloat162*)(Hi + (size_t)i * 4)     = hp0;
    *(__nv_bfloat162*)(Hi + (size_t)i * 4 + 2) = hp1;
    *(__nv_bfloat162*)(Lo + (size_t)i * 4)     = lp0;
    *(__nv_bfloat162*)(Lo + (size_t)i * 4 + 2) = lp1;
}

// W [K=4096, N=4096] fp32 -> W^T hi/lo bf16 [N, K]
__global__ __launch_bounds__(256) void wconvT(
    const float* __restrict__ W, __nv_bfloat16* __restrict__ Thi,
    __nv_bfloat16* __restrict__ Tlo)
{
    __shared__ float t[32][33];
    const int n0 = blockIdx.x * 32, k0 = blockIdx.y * 32;
    const int tx = threadIdx.x & 31, ty = threadIdx.x >> 5;   // 32 x 8
#pragma unroll
    for (int i = 0; i < 4; i++)
        t[ty + i * 8][tx] = W[(size_t)(k0 + ty + i * 8) * PD + n0 + tx];
    __syncthreads();
#pragma unroll
    for (int i = 0; i < 4; i++) {
        float v = t[tx][ty + i * 8];
        __nv_bfloat16 h = __float2bfloat16(v);
        size_t o = (size_t)(n0 + ty + i * 8) * PD + k0 + tx;
        Thi[o] = h;
        Tlo[o] = __float2bfloat16(v - __bfloat162float(h));
    }
}

// ---------------------------------------------------------------------------
// HMMA bf16-split GEMM: C[4096,4096] fp32, 3 passes over K=4096:
// (Ahi,Bhi), (Ahi,Blo), (Alo,Bhi).
// A: [M,K] row-major bf16.  B: W^T [N,K] row-major bf16 (acts as col-major
// k x n for mma row.col).  CTA tile 128x128, BK=64, 8 warps (2m x 4n),
// warp tile 64x32 = 4 m16-tiles x 4 n8-tiles. 2-stage cp.async pipeline.
// ---------------------------------------------------------------------------
#define PADK 72
#define BUFSZ (128 * PADK * 2)          // bytes per tile buffer (bf16)
#define GEMM_SMEM (4 * BUFSZ)           // A0,A1,B0,B1 = 73728

__global__ __launch_bounds__(256, 2) void gemm_mma(
    const __nv_bfloat16* __restrict__ Ahi, const __nv_bfloat16* __restrict__ Alo,
    const __nv_bfloat16* __restrict__ Bhi, const __nv_bfloat16* __restrict__ Blo,
    float* __restrict__ C)
{
    extern __shared__ char smem[];
    const uint32_t sbase = smem_u32(smem);
    const uint32_t sA[2] = {sbase, sbase + BUFSZ};
    const uint32_t sB[2] = {sbase + 2 * BUFSZ, sbase + 3 * BUFSZ};

    const int tid = threadIdx.x;
    const int lane = tid & 31, wid = tid >> 5;
    const int wm = wid >> 2;          // 0..1 -> m offset wm*64
    const int wn = wid & 3;           // 0..3 -> n offset wn*32
    const int bm = blockIdx.y * 128;
    const int bn = blockIdx.x * 128;

    const __nv_bfloat16* Aph[3] = {Ahi, Ahi, Alo};
    const __nv_bfloat16* Bph[3] = {Bhi, Blo, Bhi};

    float acc[4][4][4];
#pragma unroll
    for (int mt = 0; mt < 4; mt++)
#pragma unroll
        for (int nt = 0; nt < 4; nt++)
#pragma unroll
            for (int j = 0; j < 4; j++) acc[mt][nt][j] = 0.f;

    // loader thread mapping: row r = tid>>3 (+32*i), col c8 = (tid&7)*8
    const int lr = tid >> 3, lc = (tid & 7) * 8;
    const uint32_t soff = (uint32_t)(lr * PADK + lc) * 2;

    // ldmatrix source addresses (within a buffer)
    const uint32_t aoffA =
        (uint32_t)((wm * 64 + (lane & 15)) * PADK + (lane >> 4) * 8) * 2;
    const uint32_t aoffB =
        (uint32_t)((wn * 32 + (lane & 7)) * PADK + ((lane >> 3) & 1) * 8) * 2;

#define ISSUE_CHUNK(cc, buf) do {                                            \
        const int p_ = (cc) >> 6;                                            \
        const __nv_bfloat16* Ap_ = Aph[p_] + (size_t)bm * PD + ((cc) & 63) * 64; \
        const __nv_bfloat16* Bp_ = Bph[p_] + (size_t)bn * PD + ((cc) & 63) * 64; \
        _Pragma("unroll")                                                    \
        for (int i_ = 0; i_ < 4; i_++)                                       \
            cpa16(sA[buf] + soff + (uint32_t)(i_ * 32 * PADK * 2),           \
                  Ap_ + (size_t)(lr + i_ * 32) * PD + lc);                   \
        _Pragma("unroll")                                                    \
        for (int i_ = 0; i_ < 4; i_++)                                       \
            cpa16(sB[buf] + soff + (uint32_t)(i_ * 32 * PADK * 2),           \
                  Bp_ + (size_t)(lr + i_ * 32) * PD + lc);                   \
        CP_COMMIT();                                                         \
    } while (0)

    ISSUE_CHUNK(0, 0);

    for (int c = 0; c < 192; c++) {
        const int buf = c & 1;
        if (c + 1 < 192) {
            ISSUE_CHUNK(c + 1, buf ^ 1);
            CP_WAIT1();
        } else {
            CP_WAIT0();
        }
        __syncthreads();

#pragma unroll
        for (int ks = 0; ks < 4; ks++) {
            uint32_t ra[4][4], rb[4][2];
            const uint32_t kb = (uint32_t)(ks * 16) * 2;
#pragma unroll
            for (int mt = 0; mt < 4; mt++)
                ldmA(sA[buf] + aoffA + (uint32_t)(mt * 16 * PADK * 2) + kb,
                     ra[mt]);
#pragma unroll
            for (int nt = 0; nt < 4; nt++)
                ldmB(sB[buf] + aoffB + (uint32_t)(nt * 8 * PADK * 2) + kb,
                     rb[nt]);
#pragma unroll
            for (int mt = 0; mt < 4; mt++)
#pragma unroll
                for (int nt = 0; nt < 4; nt++)
                    mma16816(acc[mt][nt], ra[mt], rb[nt]);
        }
        __syncthreads();
    }

    // epilogue
    const int r0 = bm + wm * 64 + (lane >> 2);
    const int c0 = bn + wn * 32 + (lane & 3) * 2;
#pragma unroll
    for (int mt = 0; mt < 4; mt++) {
#pragma unroll
        for (int nt = 0; nt < 4; nt++) {
            float* p0 = C + (size_t)(r0 + mt * 16) * PD + c0 + nt * 8;
            float* p1 = p0 + 8 * PD;
            *(float2*)p0 = make_float2(acc[mt][nt][0], acc[mt][nt][1]);
            *(float2*)p1 = make_float2(acc[mt][nt][2], acc[mt][nt][3]);
        }
    }
#undef ISSUE_CHUNK
}

// ---------------------------------------------------------------------------
// RoPE, in place: x shape (B,S,H,HD), pairs (2p, 2p+1).
// ---------------------------------------------------------------------------
__global__ __launch_bounds__(256) void rope_k(
    float* __restrict__ X, const float* __restrict__ Ct, const float* __restrict__ St)
{
    int i = blockIdx.x * 256 + threadIdx.x;
    if (i >= PB * PS * PH * 64) return;
    int p = i & 63;
    int s = (i >> 11) & 2047;
    int b = i >> 22;
    int h = (i >> 6) & 31;
    float c = Ct[(s << 6) + p];
    float sn = St[(s << 6) + p];
    size_t base = (((size_t)(b << 11) + s) << 12) + (h << 7) + (p << 1);
    float x0 = X[base], x1 = X[base + 1];
    X[base]     = x0 * c - x1 * sn;
    X[base + 1] = x0 * sn + x1 * c;
}

// ---------------------------------------------------------------------------
// Adapter projection, split-K (8 slices) + reduce. Deterministic.
// ---------------------------------------------------------------------------
__global__ __launch_bounds__(256) void adapter_part(
    const float* __restrict__ Ad, const float* __restrict__ W, float* __restrict__ Part)
{
    __shared__ float sAd[PAL][512];
    const int n = blockIdx.x * 256 + threadIdx.x;
    const int k0 = blockIdx.y * 512;
    float acc[PAL];
#pragma unroll
    for (int a = 0; a < PAL; a++) acc[a] = 0.f;
    for (int i = threadIdx.x; i < PAL * 512; i += 256) {
        int a = i / 512, kk = i - a * 512;
        sAd[a][kk] = Ad[a * PD + k0 + kk];
    }
    __syncthreads();
#pragma unroll 8
    for (int kk = 0; kk < 512; kk++) {
        float w = W[(size_t)(k0 + kk) * PD + n];
#pragma unroll
        for (int a = 0; a < PAL; a++) acc[a] += sAd[a][kk] * w;
    }
#pragma unroll
    for (int a = 0; a < PAL; a++)
        Part[(size_t)blockIdx.y * (PAL * PD) + a * PD + n] = acc[a];
}

__global__ __launch_bounds__(256) void adapter_reduce(
    const float* __restrict__ Part, float* __restrict__ Out)
{
    int i = blockIdx.x * 256 + threadIdx.x;
    if (i >= PAL * PD) return;
    float s = 0.f;
#pragma unroll
    for (int j = 0; j < 8; j++) s += Part[(size_t)j * (PAL * PD) + i];
    Out[i] = s;
}

// ---------------------------------------------------------------------------
// Flash attention fp32 + fused gated adapter attention.
// ---------------------------------------------------------------------------
#define FLASH_SMEM ((3 * 64 * 132 + 64 * 68) * 4)

__global__ __launch_bounds__(256) void flashattn(
    const float* __restrict__ Q, const float* __restrict__ K,
    const float* __restrict__ V, const float* __restrict__ AK,
    const float* __restrict__ AV, const float* __restrict__ gate,
    float* __restrict__ O)
{
    extern __shared__ float sm[];
    float* Qs = sm;
    float* Ks = Qs + 64 * 132;
    float* Vs = Ks + 64 * 132;
    float* Ps = Vs + 64 * 132;

    const int qt = blockIdx.x, h = blockIdx.y, b = blockIdx.z;
    const int tid = threadIdx.x;
    const int tx = tid & 15, ty = tid >> 4;
    const float inv_sqrt = 0.088388347648318447f;

    const size_t baseQ = ((size_t)(b * PS) + qt * 64) * PD + h * PHD;
    for (int i = tid; i < 64 * 32; i += 256) {
        int r = i >> 5, c4 = (i & 31) << 2;
        *(float4*)&Qs[r * 132 + c4] =
            *(const float4*)(Q + baseQ + (size_t)r * PD + c4);
    }

    float m_[4], l_[4], acc[4][8];
#pragma unroll
    for (int qi = 0; qi < 4; qi++) {
        m_[qi] = -3.0e38f; l_[qi] = 0.f;
#pragma unroll
        for (int j = 0; j < 8; j++) acc[qi][j] = 0.f;
    }

    for (int kt = 0; kt <= qt; kt++) {
        __syncthreads();
        const size_t baseK = ((size_t)(b * PS) + kt * 64) * PD + h * PHD;
        for (int i = tid; i < 64 * 32; i += 256) {
            int r = i >> 5, c4 = (i & 31) << 2;
            *(float4*)&Ks[r * 132 + c4] =
                *(const float4*)(K + baseK + (size_t)r * PD + c4);
            *(float4*)&Vs[r * 132 + c4] =
                *(const float4*)(V + baseK + (size_t)r * PD + c4);
        }
        __syncthreads();

        float s[4][4];
#pragma unroll
        for (int qi = 0; qi < 4; qi++)
#pragma unroll
            for (int kj = 0; kj < 4; kj++) s[qi][kj] = 0.f;

#pragma unroll 4
        for (int d = 0; d < 128; d += 4) {
            float4 qv[4], kv[4];
#pragma unroll
            for (int qi = 0; qi < 4; qi++)
                qv[qi] = *(float4*)&Qs[(ty * 4 + qi) * 132 + d];
#pragma unroll
            for (int kj = 0; kj < 4; kj++)
                kv[kj] = *(float4*)&Ks[(tx * 4 + kj) * 132 + d];
#pragma unroll
            for (int qi = 0; qi < 4; qi++)
#pragma unroll
                for (int kj = 0; kj < 4; kj++) {
                    s[qi][kj] += qv[qi].x * kv[kj].x;
                    s[qi][kj] += qv[qi].y * kv[kj].y;
                    s[qi][kj] += qv[qi].z * kv[kj].z;
                    s[qi][kj] += qv[qi].w * kv[kj].w;
                }
        }

        const int qrow0 = qt * 64 + ty * 4;
#pragma unroll
        for (int qi = 0; qi < 4; qi++)
#pragma unroll
            for (int kj = 0; kj < 4; kj++) {
                float v = s[qi][kj] * inv_sqrt;
                if (kt == qt && (kt * 64 + tx * 4 + kj) > (qrow0 + qi))
                    v = -1.0e9f;
                s[qi][kj] = v;
            }

#pragma unroll
        for (int qi = 0; qi < 4; qi++) {
            float tm = fmaxf(fmaxf(s[qi][0], s[qi][1]), fmaxf(s[qi][2], s[qi][3]));
#pragma unroll
            for (int o = 8; o >= 1; o >>= 1)
                tm = fmaxf(tm, __shfl_xor_sync(0xffffffffu, tm, o));
            float mn = fmaxf(m_[qi], tm);
            float sc = __expf(m_[qi] - mn);
            float ls = 0.f;
#pragma unroll
            for (int kj = 0; kj < 4; kj++) {
                float p = __expf(s[qi][kj] - mn);
                s[qi][kj] = p;
                ls += p;
            }
#pragma unroll
            for (int o = 8; o >= 1; o >>= 1)
                ls += __shfl_xor_sync(0xffffffffu, ls, o);
            l_[qi] = l_[qi] * sc + ls;
            m_[qi] = mn;
#pragma unroll
            for (int j = 0; j < 8; j++) acc[qi][j] *= sc;
#pragma unroll
            for (int kj = 0; kj < 4; kj++)
                Ps[(ty * 4 + qi) * 68 + tx * 4 + kj] = s[qi][kj];
        }
        __syncthreads();

#pragma unroll 4
        for (int k = 0; k < 64; k++) {
            float pv0 = Ps[(ty * 4 + 0) * 68 + k];
            float pv1 = Ps[(ty * 4 + 1) * 68 + k];
            float pv2 = Ps[(ty * 4 + 2) * 68 + k];
            float pv3 = Ps[(ty * 4 + 3) * 68 + k];
            float4 v0 = *(float4*)&Vs[k * 132 + tx * 8];
            float4 v1 = *(float4*)&Vs[k * 132 + tx * 8 + 4];
            float vv[8] = {v0.x, v0.y, v0.z, v0.w, v1.x, v1.y, v1.z, v1.w};
#pragma unroll
            for (int j = 0; j < 8; j++) {
                acc[0][j] += pv0 * vv[j];
                acc[1][j] += pv1 * vv[j];
                acc[2][j] += pv2 * vv[j];
                acc[3][j] += pv3 * vv[j];
            }
        }
    }

#pragma unroll
    for (int qi = 0; qi < 4; qi++) {
        float inv = 1.f / l_[qi];
#pragma unroll
        for (int j = 0; j < 8; j++) acc[qi][j] *= inv;
    }

    const float g = gate[h];
#pragma unroll
    for (int qi = 0; qi < 4; qi++) {
        const int row = ty * 4 + qi;
        float sa[PAL];
#pragma unroll
        for (int a = 0; a < PAL; a++) {
            float part = 0.f;
#pragma unroll
            for (int j = 0; j < 8; j++)
                part += Qs[row * 132 + tx * 8 + j] *
                        AK[a * PD + h * PHD + tx * 8 + j];
#pragma unroll
            for (int o = 8; o >= 1; o >>= 1)
                part += __shfl_xor_sync(0xffffffffu, part, o);
            sa[a] = part * inv_sqrt;
        }
        float mx = sa[0];
#pragma unroll
        for (int a = 1; a < PAL; a++) mx = fmaxf(mx, sa[a]);
        float se = 0.f;
#pragma unroll
        for (int a = 0; a < PAL; a++) { sa[a] = __expf(sa[a] - mx); se += sa[a]; }
        float gs = g / se;
#pragma unroll
        for (int j = 0; j < 8; j++) {
            float add = 0.f;
#pragma unroll
            for (int a = 0; a < PAL; a++)
                add += sa[a] * AV[a * PD + h * PHD + tx * 8 + j];
            acc[qi][j] += gs * add;
        }
    }

    const size_t baseO = ((size_t)(b * PS) + qt * 64) * PD + h * PHD;
#pragma unroll
    for (int qi = 0; qi < 4; qi++) {
        int row = ty * 4 + qi;
        *(float4*)(O + baseO + (size_t)row * PD + tx * 8) =
            make_float4(acc[qi][0], acc[qi][1], acc[qi][2], acc[qi][3]);
        *(float4*)(O + baseO + (size_t)row * PD + tx * 8 + 4) =
            make_float4(acc[qi][4], acc[qi][5], acc[qi][6], acc[qi][7]);
    }
}

// ---------------------------------------------------------------------------
// kernel_launch
// ---------------------------------------------------------------------------
extern "C" void kernel_launch(void* const* d_in, const int* in_sizes, int n_in,
                              void* d_out, int out_size)
{
    (void)in_sizes; (void)n_in; (void)out_size;
    const float* x       = (const float*)d_in[0];
    const float* cosT    = (const float*)d_in[1];
    const float* sinT    = (const float*)d_in[2];
    const float* wq      = (const float*)d_in[4];
    const float* wk      = (const float*)d_in[5];
    const float* wv      = (const float*)d_in[6];
    const float* wo      = (const float*)d_in[7];
    const float* gate    = (const float*)d_in[8];
    const float* adapter = (const float*)d_in[9];
    float* out = (float*)d_out;

    float *q, *k, *v, *o, *ak, *av, *adp;
    cudaGetSymbolAddress((void**)&q,  g_q);
    cudaGetSymbolAddress((void**)&k,  g_k);
    cudaGetSymbolAddress((void**)&v,  g_v);
    cudaGetSymbolAddress((void**)&o,  g_o);
    cudaGetSymbolAddress((void**)&ak, g_ak);
    cudaGetSymbolAddress((void**)&av, g_av);
    cudaGetSymbolAddress((void**)&adp, g_adp);

    __nv_bfloat16 *xhi, *xlo, *ohi, *olo;
    __nv_bfloat16 *wqh, *wql, *wkh, *wkl, *wvh, *wvl, *woh, *wol;
    cudaGetSymbolAddress((void**)&xhi, g_xhi);
    cudaGetSymbolAddress((void**)&xlo, g_xlo);
    cudaGetSymbolAddress((void**)&ohi, g_ohi);
    cudaGetSymbolAddress((void**)&olo, g_olo);
    cudaGetSymbolAddress((void**)&wqh, g_wqT_hi);
    cudaGetSymbolAddress((void**)&wql, g_wqT_lo);
    cudaGetSymbolAddress((void**)&wkh, g_wkT_hi);
    cudaGetSymbolAddress((void**)&wkl, g_wkT_lo);
    cudaGetSymbolAddress((void**)&wvh, g_wvT_hi);
    cudaGetSymbolAddress((void**)&wvl, g_wvT_lo);
    cudaGetSymbolAddress((void**)&woh, g_woT_hi);
    cudaGetSymbolAddress((void**)&wol, g_woT_lo);

    cudaFuncSetAttribute(gemm_mma, cudaFuncAttributeMaxDynamicSharedMemorySize,
                         GEMM_SMEM);
    cudaFuncSetAttribute(flashattn, cudaFuncAttributeMaxDynamicSharedMemorySize,
                         FLASH_SMEM);

    // bf16 conversions
    dim3 wcg(PD / 32, PD / 32);
    wconvT<<<wcg, 256>>>(wq, wqh, wql);
    wconvT<<<wcg, 256>>>(wk, wkh, wkl);
    wconvT<<<wcg, 256>>>(wv, wvh, wvl);
    wconvT<<<wcg, 256>>>(wo, woh, wol);
    split_bf16<<<NELEM / 4 / 256, 256>>>(x, xhi, xlo, NELEM / 4);

    // projections on tensor cores (warp mma)
    dim3 gg(PD / 128, PM / 128);   // 32 x 32
    gemm_mma<<<gg, 256, GEMM_SMEM>>>(xhi, xlo, wqh, wql, q);
    gemm_mma<<<gg, 256, GEMM_SMEM>>>(xhi, xlo, wkh, wkl, k);
    gemm_mma<<<gg, 256, GEMM_SMEM>>>(xhi, xlo, wvh, wvl, v);

    // adapter projections (fp32, split-K)
    adapter_part<<<dim3(PD / 256, 8), 256>>>(adapter, wk, adp);
    adapter_reduce<<<(PAL * PD + 255) / 256, 256>>>(adp, ak);
    adapter_part<<<dim3(PD / 256, 8), 256>>>(adapter, wv, adp);
    adapter_reduce<<<(PAL * PD + 255) / 256, 256>>>(adp, av);

    // RoPE
    const int ropeN = PB * PS * PH * 64;
    rope_k<<<ropeN / 256, 256>>>(q, cosT, sinT);
    rope_k<<<ropeN / 256, 256>>>(k, cosT, sinT);

    // attention
    flashattn<<<dim3(PS / 64, PH, PB), 256, FLASH_SMEM>>>(q, k, v, ak, av, gate, o);

    // output projection
    split_bf16<<<NELEM / 4 / 256, 256>>>(o, ohi, olo, NELEM / 4);
    gemm_mma<<<gg, 256, GEMM_SMEM>>>(ohi, olo, woh, wol, out);
}

// round 5
// speedup vs baseline: 2.8363x; 1.5762x over previous
#include <cuda_runtime.h>
#include <cuda_bf16.h>
#include <cuda_fp16.h>
#include <cstdint>
#include <math.h>

// Problem constants
#define PB 2
#define PS 2048
#define PD 4096
#define PH 32
#define PHD 128
#define PAL 10
#define PM (PB*PS)          // 4096 rows
#define NELEM (PB*PS*PD)    // 16777216

// ---------------------------------------------------------------------------
// Scratch (device globals — no allocation APIs allowed)
// ---------------------------------------------------------------------------
__device__ float g_q[NELEM];
__device__ float g_k[NELEM];
__device__ float g_v[NELEM];
__device__ float g_o[NELEM];
__device__ float g_ak[PAL*PD];
__device__ float g_av[PAL*PD];
__device__ float g_adp[8*PAL*PD];
__device__ float g_aw[PM*PH*PAL];       // gated adapter softmax weights

__device__ __nv_bfloat16 g_xhi[NELEM];
__device__ __nv_bfloat16 g_xlo[NELEM];
__device__ __nv_bfloat16 g_ohi[NELEM];
__device__ __nv_bfloat16 g_olo[NELEM];
__device__ __nv_bfloat16 g_wqT_hi[PD*PD];
__device__ __nv_bfloat16 g_wqT_lo[PD*PD];
__device__ __nv_bfloat16 g_wkT_hi[PD*PD];
__device__ __nv_bfloat16 g_wkT_lo[PD*PD];
__device__ __nv_bfloat16 g_wvT_hi[PD*PD];
__device__ __nv_bfloat16 g_wvT_lo[PD*PD];
__device__ __nv_bfloat16 g_woT_hi[PD*PD];
__device__ __nv_bfloat16 g_woT_lo[PD*PD];

// fp16 operands for HMMA attention
__device__ __half g_qh[NELEM];
__device__ __half g_ql[NELEM];
__device__ __half g_kh[NELEM];
__device__ __half g_kl[NELEM];
__device__ __half g_vh[NELEM];

// ---------------------------------------------------------------------------
// Base-target PTX helpers (no tcgen05: harness targets sm_103 base).
// ---------------------------------------------------------------------------
__device__ __forceinline__ uint32_t smem_u32(const void* p) {
    uint32_t a;
    asm("{ .reg .u64 t; cvta.to.shared.u64 t, %1; cvt.u32.u64 %0, t; }"
        : "=r"(a) : "l"(p));
    return a;
}
__device__ __forceinline__ void cpa16(uint32_t s, const void* g) {
    asm volatile("cp.async.ca.shared.global [%0], [%1], 16;" :: "r"(s), "l"(g));
}
#define CP_COMMIT() asm volatile("cp.async.commit_group;" ::: "memory")
#define CP_WAIT1()  asm volatile("cp.async.wait_group 1;" ::: "memory")
#define CP_WAIT0()  asm volatile("cp.async.wait_group 0;" ::: "memory")

__device__ __forceinline__ void ldmA(uint32_t a, uint32_t r[4]) {
    asm volatile("ldmatrix.sync.aligned.m8n8.x4.shared.b16 {%0,%1,%2,%3}, [%4];"
        : "=r"(r[0]), "=r"(r[1]), "=r"(r[2]), "=r"(r[3]) : "r"(a));
}
__device__ __forceinline__ void ldmB(uint32_t a, uint32_t r[2]) {
    asm volatile("ldmatrix.sync.aligned.m8n8.x2.shared.b16 {%0,%1}, [%2];"
        : "=r"(r[0]), "=r"(r[1]) : "r"(a));
}
__device__ __forceinline__ void ldmB4(uint32_t a, uint32_t r[4]) {
    asm volatile("ldmatrix.sync.aligned.m8n8.x4.shared.b16 {%0,%1,%2,%3}, [%4];"
        : "=r"(r[0]), "=r"(r[1]), "=r"(r[2]), "=r"(r[3]) : "r"(a));
}
__device__ __forceinline__ void ldmB4t(uint32_t a, uint32_t r[4]) {
    asm volatile("ldmatrix.sync.aligned.m8n8.x4.trans.shared.b16 {%0,%1,%2,%3}, [%4];"
        : "=r"(r[0]), "=r"(r[1]), "=r"(r[2]), "=r"(r[3]) : "r"(a));
}
__device__ __forceinline__ void mma16816(float d[4], const uint32_t a[4],
                                         const uint32_t b[2]) {
    asm volatile(
        "mma.sync.aligned.m16n8k16.row.col.f32.bf16.bf16.f32 "
        "{%0,%1,%2,%3}, {%4,%5,%6,%7}, {%8,%9}, {%0,%1,%2,%3};"
        : "+f"(d[0]), "+f"(d[1]), "+f"(d[2]), "+f"(d[3])
        : "r"(a[0]), "r"(a[1]), "r"(a[2]), "r"(a[3]), "r"(b[0]), "r"(b[1]));
}
__device__ __forceinline__ void mma16816h(float d[4], const uint32_t a[4],
                                          const uint32_t b[2]) {
    asm volatile(
        "mma.sync.aligned.m16n8k16.row.col.f32.f16.f16.f32 "
        "{%0,%1,%2,%3}, {%4,%5,%6,%7}, {%8,%9}, {%0,%1,%2,%3};"
        : "+f"(d[0]), "+f"(d[1]), "+f"(d[2]), "+f"(d[3])
        : "r"(a[0]), "r"(a[1]), "r"(a[2]), "r"(a[3]), "r"(b[0]), "r"(b[1]));
}
__device__ __forceinline__ uint32_t packh2(float a, float b) {
    __half2 h = __floats2half2_rn(a, b);
    return *(uint32_t*)&h;
}

// ---------------------------------------------------------------------------
// Conversions
// ---------------------------------------------------------------------------
__global__ __launch_bounds__(256) void split_bf16(
    const float* __restrict__ X, __nv_bfloat16* __restrict__ Hi,
    __nv_bfloat16* __restrict__ Lo, int n4)
{
    int i = blockIdx.x * 256 + threadIdx.x;
    if (i >= n4) return;
    float4 v = *(const float4*)(X + (size_t)i * 4);
    __nv_bfloat16 h0 = __float2bfloat16(v.x);
    __nv_bfloat16 h1 = __float2bfloat16(v.y);
    __nv_bfloat16 h2 = __float2bfloat16(v.z);
    __nv_bfloat16 h3 = __float2bfloat16(v.w);
    __nv_bfloat162 hp0; hp0.x = h0; hp0.y = h1;
    __nv_bfloat162 hp1; hp1.x = h2; hp1.y = h3;
    __nv_bfloat162 lp0;
    lp0.x = __float2bfloat16(v.x - __bfloat162float(h0));
    lp0.y = __float2bfloat16(v.y - __bfloat162float(h1));
    __nv_bfloat162 lp1;
    lp1.x = __float2bfloat16(v.z - __bfloat162float(h2));
    lp1.y = __float2bfloat16(v.w - __bfloat162float(h3));
    *(__nv_bfloat162*)(Hi + (size_t)i * 4)     = hp0;
    *(__nv_bfloat162*)(Hi + (size_t)i * 4 + 2) = hp1;
    *(__nv_bfloat162*)(Lo + (size_t)i * 4)     = lp0;
    *(__nv_bfloat162*)(Lo + (size_t)i * 4 + 2) = lp1;
}

__global__ __launch_bounds__(256) void split_fp16(
    const float* __restrict__ X, __half* __restrict__ Hi,
    __half* __restrict__ Lo, int n4)
{
    int i = blockIdx.x * 256 + threadIdx.x;
    if (i >= n4) return;
    float4 v = *(const float4*)(X + (size_t)i * 4);
    __half h0 = __float2half_rn(v.x), h1 = __float2half_rn(v.y);
    __half h2 = __float2half_rn(v.z), h3 = __float2half_rn(v.w);
    __half2 hp0; hp0.x = h0; hp0.y = h1;
    __half2 hp1; hp1.x = h2; hp1.y = h3;
    __half2 lp0;
    lp0.x = __float2half_rn(v.x - __half2float(h0));
    lp0.y = __float2half_rn(v.y - __half2float(h1));
    __half2 lp1;
    lp1.x = __float2half_rn(v.z - __half2float(h2));
    lp1.y = __float2half_rn(v.w - __half2float(h3));
    *(__half2*)(Hi + (size_t)i * 4)     = hp0;
    *(__half2*)(Hi + (size_t)i * 4 + 2) = hp1;
    *(__half2*)(Lo + (size_t)i * 4)     = lp0;
    *(__half2*)(Lo + (size_t)i * 4 + 2) = lp1;
}

__global__ __launch_bounds__(256) void cvt_fp16(
    const float* __restrict__ X, __half* __restrict__ H, int n4)
{
    int i = blockIdx.x * 256 + threadIdx.x;
    if (i >= n4) return;
    float4 v = *(const float4*)(X + (size_t)i * 4);
    __half2 p0; p0.x = __float2half_rn(v.x); p0.y = __float2half_rn(v.y);
    __half2 p1; p1.x = __float2half_rn(v.z); p1.y = __float2half_rn(v.w);
    *(__half2*)(H + (size_t)i * 4)     = p0;
    *(__half2*)(H + (size_t)i * 4 + 2) = p1;
}

// W [K=4096, N=4096] fp32 -> W^T hi/lo bf16 [N, K]
__global__ __launch_bounds__(256) void wconvT(
    const float* __restrict__ W, __nv_bfloat16* __restrict__ Thi,
    __nv_bfloat16* __restrict__ Tlo)
{
    __shared__ float t[32][33];
    const int n0 = blockIdx.x * 32, k0 = blockIdx.y * 32;
    const int tx = threadIdx.x & 31, ty = threadIdx.x >> 5;   // 32 x 8
#pragma unroll
    for (int i = 0; i < 4; i++)
        t[ty + i * 8][tx] = W[(size_t)(k0 + ty + i * 8) * PD + n0 + tx];
    __syncthreads();
#pragma unroll
    for (int i = 0; i < 4; i++) {
        float v = t[tx][ty + i * 8];
        __nv_bfloat16 h = __float2bfloat16(v);
        size_t o = (size_t)(n0 + ty + i * 8) * PD + k0 + tx;
        Thi[o] = h;
        Tlo[o] = __float2bfloat16(v - __bfloat162float(h));
    }
}

// ---------------------------------------------------------------------------
// HMMA bf16-split GEMM (unchanged from round 4).
// ---------------------------------------------------------------------------
#define PADK 72
#define BUFSZ (128 * PADK * 2)
#define GEMM_SMEM (4 * BUFSZ)

__global__ __launch_bounds__(256, 2) void gemm_mma(
    const __nv_bfloat16* __restrict__ Ahi, const __nv_bfloat16* __restrict__ Alo,
    const __nv_bfloat16* __restrict__ Bhi, const __nv_bfloat16* __restrict__ Blo,
    float* __restrict__ C)
{
    extern __shared__ char smem[];
    const uint32_t sbase = smem_u32(smem);
    const uint32_t sA[2] = {sbase, sbase + BUFSZ};
    const uint32_t sB[2] = {sbase + 2 * BUFSZ, sbase + 3 * BUFSZ};

    const int tid = threadIdx.x;
    const int lane = tid & 31, wid = tid >> 5;
    const int wm = wid >> 2;
    const int wn = wid & 3;
    const int bm = blockIdx.y * 128;
    const int bn = blockIdx.x * 128;

    const __nv_bfloat16* Aph[3] = {Ahi, Ahi, Alo};
    const __nv_bfloat16* Bph[3] = {Bhi, Blo, Bhi};

    float acc[4][4][4];
#pragma unroll
    for (int mt = 0; mt < 4; mt++)
#pragma unroll
        for (int nt = 0; nt < 4; nt++)
#pragma unroll
            for (int j = 0; j < 4; j++) acc[mt][nt][j] = 0.f;

    const int lr = tid >> 3, lc = (tid & 7) * 8;
    const uint32_t soff = (uint32_t)(lr * PADK + lc) * 2;

    const uint32_t aoffA =
        (uint32_t)((wm * 64 + (lane & 15)) * PADK + (lane >> 4) * 8) * 2;
    const uint32_t aoffB =
        (uint32_t)((wn * 32 + (lane & 7)) * PADK + ((lane >> 3) & 1) * 8) * 2;

#define ISSUE_CHUNK(cc, buf) do {                                            \
        const int p_ = (cc) >> 6;                                            \
        const __nv_bfloat16* Ap_ = Aph[p_] + (size_t)bm * PD + ((cc) & 63) * 64; \
        const __nv_bfloat16* Bp_ = Bph[p_] + (size_t)bn * PD + ((cc) & 63) * 64; \
        _Pragma("unroll")                                                    \
        for (int i_ = 0; i_ < 4; i_++)                                       \
            cpa16(sA[buf] + soff + (uint32_t)(i_ * 32 * PADK * 2),           \
                  Ap_ + (size_t)(lr + i_ * 32) * PD + lc);                   \
        _Pragma("unroll")                                                    \
        for (int i_ = 0; i_ < 4; i_++)                                       \
            cpa16(sB[buf] + soff + (uint32_t)(i_ * 32 * PADK * 2),           \
                  Bp_ + (size_t)(lr + i_ * 32) * PD + lc);                   \
        CP_COMMIT();                                                         \
    } while (0)

    ISSUE_CHUNK(0, 0);

    for (int c = 0; c < 192; c++) {
        const int buf = c & 1;
        if (c + 1 < 192) {
            ISSUE_CHUNK(c + 1, buf ^ 1);
            CP_WAIT1();
        } else {
            CP_WAIT0();
        }
        __syncthreads();

#pragma unroll
        for (int ks = 0; ks < 4; ks++) {
            uint32_t ra[4][4], rb[4][2];
            const uint32_t kb = (uint32_t)(ks * 16) * 2;
#pragma unroll
            for (int mt = 0; mt < 4; mt++)
                ldmA(sA[buf] + aoffA + (uint32_t)(mt * 16 * PADK * 2) + kb,
                     ra[mt]);
#pragma unroll
            for (int nt = 0; nt < 4; nt++)
                ldmB(sB[buf] + aoffB + (uint32_t)(nt * 8 * PADK * 2) + kb,
                     rb[nt]);
#pragma unroll
            for (int mt = 0; mt < 4; mt++)
#pragma unroll
                for (int nt = 0; nt < 4; nt++)
                    mma16816(acc[mt][nt], ra[mt], rb[nt]);
        }
        __syncthreads();
    }

    const int r0 = bm + wm * 64 + (lane >> 2);
    const int c0 = bn + wn * 32 + (lane & 3) * 2;
#pragma unroll
    for (int mt = 0; mt < 4; mt++) {
#pragma unroll
        for (int nt = 0; nt < 4; nt++) {
            float* p0 = C + (size_t)(r0 + mt * 16) * PD + c0 + nt * 8;
            float* p1 = p0 + 8 * PD;
            *(float2*)p0 = make_float2(acc[mt][nt][0], acc[mt][nt][1]);
            *(float2*)p1 = make_float2(acc[mt][nt][2], acc[mt][nt][3]);
        }
    }
#undef ISSUE_CHUNK
}

// ---------------------------------------------------------------------------
// RoPE in place
// ---------------------------------------------------------------------------
__global__ __launch_bounds__(256) void rope_k(
    float* __restrict__ X, const float* __restrict__ Ct, const float* __restrict__ St)
{
    int i = blockIdx.x * 256 + threadIdx.x;
    if (i >= PB * PS * PH * 64) return;
    int p = i & 63;
    int s = (i >> 11) & 2047;
    int b = i >> 22;
    int h = (i >> 6) & 31;
    float c = Ct[(s << 6) + p];
    float sn = St[(s << 6) + p];
    size_t base = (((size_t)(b << 11) + s) << 12) + (h << 7) + (p << 1);
    float x0 = X[base], x1 = X[base + 1];
    X[base]     = x0 * c - x1 * sn;
    X[base + 1] = x0 * sn + x1 * c;
}

// ---------------------------------------------------------------------------
// Adapter projection split-K + reduce
// ---------------------------------------------------------------------------
__global__ __launch_bounds__(256) void adapter_part(
    const float* __restrict__ Ad, const float* __restrict__ W, float* __restrict__ Part)
{
    __shared__ float sAd[PAL][512];
    const int n = blockIdx.x * 256 + threadIdx.x;
    const int k0 = blockIdx.y * 512;
    float acc[PAL];
#pragma unroll
    for (int a = 0; a < PAL; a++) acc[a] = 0.f;
    for (int i = threadIdx.x; i < PAL * 512; i += 256) {
        int a = i / 512, kk = i - a * 512;
        sAd[a][kk] = Ad[a * PD + k0 + kk];
    }
    __syncthreads();
#pragma unroll 8
    for (int kk = 0; kk < 512; kk++) {
        float w = W[(size_t)(k0 + kk) * PD + n];
#pragma unroll
        for (int a = 0; a < PAL; a++) acc[a] += sAd[a][kk] * w;
    }
#pragma unroll
    for (int a = 0; a < PAL; a++)
        Part[(size_t)blockIdx.y * (PAL * PD) + a * PD + n] = acc[a];
}

__global__ __launch_bounds__(256) void adapter_reduce(
    const float* __restrict__ Part, float* __restrict__ Out)
{
    int i = blockIdx.x * 256 + threadIdx.x;
    if (i >= PAL * PD) return;
    float s = 0.f;
#pragma unroll
    for (int j = 0; j < 8; j++) s += Part[(size_t)j * (PAL * PD) + i];
    Out[i] = s;
}

// ---------------------------------------------------------------------------
// Adapter attention weights: AW[row, h, a] = gate[h]*softmax_a(q . ak / sqrt)
// One warp per (row, h). 8 warps per block.
// ---------------------------------------------------------------------------
__global__ __launch_bounds__(256) void adapter_scores(
    const float* __restrict__ Q, const float* __restrict__ AK,
    const float* __restrict__ gate, float* __restrict__ AW)
{
    const int wid = threadIdx.x >> 5, lane = threadIdx.x & 31;
    const int id = blockIdx.x * 8 + wid;          // 0 .. PM*PH-1
    const int row = id >> 5, h = id & 31;
    const float isq = 0.088388347648318447f;

    const float* qp = Q + (size_t)row * PD + h * PHD;
    float4 qv = *(const float4*)(qp + lane * 4);

    float sa[PAL];
#pragma unroll
    for (int a = 0; a < PAL; a++) {
        float4 kv = *(const float4*)(AK + (size_t)a * PD + h * PHD + lane * 4);
        float d = qv.x * kv.x + qv.y * kv.y + qv.z * kv.z + qv.w * kv.w;
#pragma unroll
        for (int o = 16; o >= 1; o >>= 1)
            d += __shfl_xor_sync(0xffffffffu, d, o);
        sa[a] = d * isq;
    }
    float mx = sa[0];
#pragma unroll
    for (int a = 1; a < PAL; a++) mx = fmaxf(mx, sa[a]);
    float se = 0.f;
#pragma unroll
    for (int a = 0; a < PAL; a++) { sa[a] = __expf(sa[a] - mx); se += sa[a]; }
    float gs = gate[h] / se;
    if (lane < PAL)
        AW[(size_t)row * (PH * PAL) + h * PAL + lane] = gs * sa[lane];
}

// ---------------------------------------------------------------------------
// Flash attention on HMMA fp16.
// CTA: 256 threads (8 warps), tile BM=128 (warp m16), BN=64, HD=128.
// QK^T: 3-pass fp16 split (Qhi in regs, Qlo in smem).  PV: single fp16.
// K/V tiles double-buffered cp.async. FA2 in-register P reuse.
// ---------------------------------------------------------------------------
#define FPADH 136
#define KVROW (FPADH * 2)                 // 272 bytes per smem row
#define KBUF (64 * KVROW)                 // 17408
#define FBUF (3 * KBUF)                   // khi, klo, v per stage
#define FQLO_OFF (2 * FBUF)               // 104448
#define FAV_OFF (FQLO_OFF + 128 * KVROW)  // 139264
#define FLASH2_SMEM (FAV_OFF + PAL * PHD * 4)   // 144384

__global__ __launch_bounds__(256) void flashmma(
    const __half* __restrict__ QH, const __half* __restrict__ QL,
    const __half* __restrict__ KH, const __half* __restrict__ KL,
    const __half* __restrict__ VH, const float* __restrict__ AW,
    const float* __restrict__ AV, float* __restrict__ O)
{
    extern __shared__ char smem[];
    const int qt = blockIdx.x, h = blockIdx.y, b = blockIdx.z;
    const int tid = threadIdx.x;
    const int lane = tid & 31, w = tid >> 5;
    const float isq = 0.088388347648318447f;

    const uint32_t sb = smem_u32(smem);
    const uint32_t sKV[2] = {sb, sb + FBUF};
    const uint32_t sQlo = sb + FQLO_OFF;
    float* av_s = (float*)(smem + FAV_OFF);

    // AV tile for this head into smem
    for (int i = tid; i < PAL * PHD; i += 256)
        av_s[i] = AV[(size_t)(i >> 7) * PD + h * PHD + (i & 127)];

    // ---- Prologue: load Q (hi via sKV[0] staging, lo persistent) ----
    {
        const size_t qbase = ((size_t)(b * PS) + qt * 128) * PD + h * PHD;
#pragma unroll
        for (int i = 0; i < 8; i++) {
            int idx = tid + i * 256;              // 0..2047
            int r = idx >> 4, c = idx & 15;
            cpa16(sKV[0] + (uint32_t)(r * KVROW + c * 16),
                  QH + qbase + (size_t)r * PD + c * 8);
            cpa16(sQlo + (uint32_t)(r * KVROW + c * 16),
                  QL + qbase + (size_t)r * PD + c * 8);
        }
        CP_COMMIT();
        CP_WAIT0();
    }
    __syncthreads();

    // Qhi fragments (per warp: 16 rows x 128 k = 8 k16 chunks)
    uint32_t qf[8][4];
    {
        const uint32_t base =
            sKV[0] + (uint32_t)((w * 16 + (lane & 15)) * KVROW + (lane >> 4) * 16);
#pragma unroll
        for (int ks = 0; ks < 8; ks++)
            ldmA(base + (uint32_t)(ks * 32), qf[ks]);
    }
    __syncthreads();   // done reading staging before KV prefetch overwrites

    // output accumulators: 16 n8 frags (128 cols)
    float oA[16][4];
#pragma unroll
    for (int nj = 0; nj < 16; nj++)
#pragma unroll
        for (int j = 0; j < 4; j++) oA[nj][j] = 0.f;
    float m0 = -3.0e38f, m1 = -3.0e38f, l0 = 0.f, l1 = 0.f;

    const int nt = 2 * qt + 2;
    const int r0g = qt * 128 + w * 16 + (lane >> 2);
    const int r1g = r0g + 8;
    const int rowmax = qt * 128 + w * 16 + 15;

#define ISSUE_KV(tt, bb) do {                                                \
        const size_t kb_ = ((size_t)(b * PS) + (tt) * 64) * PD + h * PHD;    \
        _Pragma("unroll")                                                    \
        for (int i_ = 0; i_ < 4; i_++) {                                     \
            int idx_ = tid + i_ * 256;                                       \
            int r_ = idx_ >> 4, c_ = idx_ & 15;                              \
            uint32_t so_ = (uint32_t)(r_ * KVROW + c_ * 16);                 \
            const size_t go_ = kb_ + (size_t)r_ * PD + c_ * 8;               \
            cpa16(sKV[bb] + so_,            KH + go_);                       \
            cpa16(sKV[bb] + KBUF + so_,     KL + go_);                       \
            cpa16(sKV[bb] + 2 * KBUF + so_, VH + go_);                       \
        }                                                                    \
        CP_COMMIT();                                                         \
    } while (0)

    ISSUE_KV(0, 0);

    for (int kt = 0; kt < nt; kt++) {
        const int buf = kt & 1;
        if (kt + 1 < nt) { ISSUE_KV(kt + 1, buf ^ 1); CP_WAIT1(); }
        else             { CP_WAIT0(); }
        __syncthreads();

        if (kt * 64 <= rowmax) {
            // ---- S = Q K^T (3-pass fp16 split), 16x64 per warp ----
            float s[8][4];
#pragma unroll
            for (int nj = 0; nj < 8; nj++)
#pragma unroll
                for (int j = 0; j < 4; j++) s[nj][j] = 0.f;

            const uint32_t kbase =
                sKV[buf] + (uint32_t)(((lane & 7) + (lane >> 4) * 8) * KVROW +
                                      ((lane >> 3) & 1) * 16);
            const uint32_t qlbase =
                sQlo + (uint32_t)((w * 16 + (lane & 15)) * KVROW + (lane >> 4) * 16);

#pragma unroll
            for (int ks = 0; ks < 8; ks++) {
                uint32_t kf[8][2], kl[8][2], qlo[4];
#pragma unroll
                for (int p = 0; p < 4; p++) {
                    uint32_t t4[4];
                    uint32_t ad = kbase + (uint32_t)(p * 16 * KVROW + ks * 32);
                    ldmB4(ad, t4);
                    kf[2 * p][0] = t4[0]; kf[2 * p][1] = t4[1];
                    kf[2 * p + 1][0] = t4[2]; kf[2 * p + 1][1] = t4[3];
                    ldmB4(ad + KBUF, t4);
                    kl[2 * p][0] = t4[0]; kl[2 * p][1] = t4[1];
                    kl[2 * p + 1][0] = t4[2]; kl[2 * p + 1][1] = t4[3];
                }
                ldmA(qlbase + (uint32_t)(ks * 32), qlo);
#pragma unroll
                for (int nj = 0; nj < 8; nj++) {
                    mma16816h(s[nj], qf[ks], kf[nj]);
                    mma16816h(s[nj], qf[ks], kl[nj]);
                    mma16816h(s[nj], qlo,    kf[nj]);
                }
            }

            // ---- scale + causal mask ----
            const bool diag = (kt * 64 + 63 > rowmax - 15 + (w * 0)) &&
                              (kt * 64 + 63 > qt * 128 + w * 16);
#pragma unroll
            for (int nj = 0; nj < 8; nj++) {
                const int cb = kt * 64 + nj * 8 + (lane & 3) * 2;
                s[nj][0] *= isq; s[nj][1] *= isq;
                s[nj][2] *= isq; s[nj][3] *= isq;
                if (diag) {
                    if (cb     > r0g) s[nj][0] = -1.0e9f;
                    if (cb + 1 > r0g) s[nj][1] = -1.0e9f;
                    if (cb     > r1g) s[nj][2] = -1.0e9f;
                    if (cb + 1 > r1g) s[nj][3] = -1.0e9f;
                }
            }

            // ---- online softmax ----
            float mx0 = -3.0e38f, mx1 = -3.0e38f;
#pragma unroll
            for (int nj = 0; nj < 8; nj++) {
                mx0 = fmaxf(mx0, fmaxf(s[nj][0], s[nj][1]));
                mx1 = fmaxf(mx1, fmaxf(s[nj][2], s[nj][3]));
            }
#pragma unroll
            for (int o = 1; o <= 2; o <<= 1) {
                mx0 = fmaxf(mx0, __shfl_xor_sync(0xffffffffu, mx0, o));
                mx1 = fmaxf(mx1, __shfl_xor_sync(0xffffffffu, mx1, o));
            }
            float mn0 = fmaxf(m0, mx0), mn1 = fmaxf(m1, mx1);
            float sc0 = __expf(m0 - mn0), sc1 = __expf(m1 - mn1);
            float ls0 = 0.f, ls1 = 0.f;
#pragma unroll
            for (int nj = 0; nj < 8; nj++) {
                s[nj][0] = __expf(s[nj][0] - mn0);
                s[nj][1] = __expf(s[nj][1] - mn0);
                s[nj][2] = __expf(s[nj][2] - mn1);
                s[nj][3] = __expf(s[nj][3] - mn1);
                ls0 += s[nj][0] + s[nj][1];
                ls1 += s[nj][2] + s[nj][3];
            }
#pragma unroll
            for (int o = 1; o <= 2; o <<= 1) {
                ls0 += __shfl_xor_sync(0xffffffffu, ls0, o);
                ls1 += __shfl_xor_sync(0xffffffffu, ls1, o);
            }
            l0 = l0 * sc0 + ls0; m0 = mn0;
            l1 = l1 * sc1 + ls1; m1 = mn1;
#pragma unroll
            for (int nj = 0; nj < 16; nj++) {
                oA[nj][0] *= sc0; oA[nj][1] *= sc0;
                oA[nj][2] *= sc1; oA[nj][3] *= sc1;
            }

            // ---- P -> fp16 A-frags, PV mma ----
            uint32_t aP[4][4];
#pragma unroll
            for (int t = 0; t < 4; t++) {
                aP[t][0] = packh2(s[2 * t][0],     s[2 * t][1]);
                aP[t][1] = packh2(s[2 * t][2],     s[2 * t][3]);
                aP[t][2] = packh2(s[2 * t + 1][0], s[2 * t + 1][1]);
                aP[t][3] = packh2(s[2 * t + 1][2], s[2 * t + 1][3]);
            }
            const uint32_t vbase = sKV[buf] + 2 * KBUF +
                (uint32_t)((lane & 15) * KVROW + (lane >> 4) * 16);
#pragma unroll
            for (int t = 0; t < 4; t++) {
#pragma unroll
                for (int jp = 0; jp < 8; jp++) {
                    uint32_t vb[4];
                    ldmB4t(vbase + (uint32_t)(16 * t * KVROW + jp * 32), vb);
                    mma16816h(oA[2 * jp],     aP[t], vb);
                    mma16816h(oA[2 * jp + 1], aP[t], vb + 2);
                }
            }
        }
        __syncthreads();
    }
#undef ISSUE_KV

    // ---- epilogue: normalize + gated adapter AV add + store ----
    const float inv0 = 1.f / l0, inv1 = 1.f / l1;
    float w0[PAL], w1[PAL];
    {
        const float* p0 = AW + ((size_t)(b * PS) + r0g) * (PH * PAL) + h * PAL;
        const float* p1 = AW + ((size_t)(b * PS) + r1g) * (PH * PAL) + h * PAL;
#pragma unroll
        for (int a = 0; a < PAL; a++) { w0[a] = p0[a]; w1[a] = p1[a]; }
    }
#pragma unroll
    for (int nj = 0; nj < 16; nj++) {
        const int c0 = nj * 8 + (lane & 3) * 2;
        float a00 = 0.f, a01 = 0.f, a10 = 0.f, a11 = 0.f;
#pragma unroll
        for (int a = 0; a < PAL; a++) {
            float va0 = av_s[a * PHD + c0], va1 = av_s[a * PHD + c0 + 1];
            a00 += w0[a] * va0; a01 += w0[a] * va1;
            a10 += w1[a] * va0; a11 += w1[a] * va1;
        }
        oA[nj][0] = oA[nj][0] * inv0 + a00;
        oA[nj][1] = oA[nj][1] * inv0 + a01;
        oA[nj][2] = oA[nj][2] * inv1 + a10;
        oA[nj][3] = oA[nj][3] * inv1 + a11;
    }
    {
        float* o0 = O + ((size_t)(b * PS) + r0g) * PD + h * PHD + (lane & 3) * 2;
        float* o1 = O + ((size_t)(b * PS) + r1g) * PD + h * PHD + (lane & 3) * 2;
#pragma unroll
        for (int nj = 0; nj < 16; nj++) {
            *(float2*)(o0 + nj * 8) = make_float2(oA[nj][0], oA[nj][1]);
            *(float2*)(o1 + nj * 8) = make_float2(oA[nj][2], oA[nj][3]);
        }
    }
}

// ---------------------------------------------------------------------------
// kernel_launch
// ---------------------------------------------------------------------------
extern "C" void kernel_launch(void* const* d_in, const int* in_sizes, int n_in,
                              void* d_out, int out_size)
{
    (void)in_sizes; (void)n_in; (void)out_size;
    const float* x       = (const float*)d_in[0];
    const float* cosT    = (const float*)d_in[1];
    const float* sinT    = (const float*)d_in[2];
    const float* wq      = (const float*)d_in[4];
    const float* wk      = (const float*)d_in[5];
    const float* wv      = (const float*)d_in[6];
    const float* wo      = (const float*)d_in[7];
    const float* gate    = (const float*)d_in[8];
    const float* adapter = (const float*)d_in[9];
    float* out = (float*)d_out;

    float *q, *k, *v, *o, *ak, *av, *adp, *aw;
    cudaGetSymbolAddress((void**)&q,  g_q);
    cudaGetSymbolAddress((void**)&k,  g_k);
    cudaGetSymbolAddress((void**)&v,  g_v);
    cudaGetSymbolAddress((void**)&o,  g_o);
    cudaGetSymbolAddress((void**)&ak, g_ak);
    cudaGetSymbolAddress((void**)&av, g_av);
    cudaGetSymbolAddress((void**)&adp, g_adp);
    cudaGetSymbolAddress((void**)&aw, g_aw);

    __nv_bfloat16 *xhi, *xlo, *ohi, *olo;
    __nv_bfloat16 *wqh, *wql, *wkh, *wkl, *wvh, *wvl, *woh, *wol;
    cudaGetSymbolAddress((void**)&xhi, g_xhi);
    cudaGetSymbolAddress((void**)&xlo, g_xlo);
    cudaGetSymbolAddress((void**)&ohi, g_ohi);
    cudaGetSymbolAddress((void**)&olo, g_olo);
    cudaGetSymbolAddress((void**)&wqh, g_wqT_hi);
    cudaGetSymbolAddress((void**)&wql, g_wqT_lo);
    cudaGetSymbolAddress((void**)&wkh, g_wkT_hi);
    cudaGetSymbolAddress((void**)&wkl, g_wkT_lo);
    cudaGetSymbolAddress((void**)&wvh, g_wvT_hi);
    cudaGetSymbolAddress((void**)&wvl, g_wvT_lo);
    cudaGetSymbolAddress((void**)&woh, g_woT_hi);
    cudaGetSymbolAddress((void**)&wol, g_woT_lo);

    __half *qh16, *ql16, *kh16, *kl16, *vh16;
    cudaGetSymbolAddress((void**)&qh16, g_qh);
    cudaGetSymbolAddress((void**)&ql16, g_ql);
    cudaGetSymbolAddress((void**)&kh16, g_kh);
    cudaGetSymbolAddress((void**)&kl16, g_kl);
    cudaGetSymbolAddress((void**)&vh16, g_vh);

    cudaFuncSetAttribute(gemm_mma, cudaFuncAttributeMaxDynamicSharedMemorySize,
                         GEMM_SMEM);
    cudaFuncSetAttribute(flashmma, cudaFuncAttributeMaxDynamicSharedMemorySize,
                         FLASH2_SMEM);

    // bf16 conversions for projection GEMMs
    dim3 wcg(PD / 32, PD / 32);
    wconvT<<<wcg, 256>>>(wq, wqh, wql);
    wconvT<<<wcg, 256>>>(wk, wkh, wkl);
    wconvT<<<wcg, 256>>>(wv, wvh, wvl);
    wconvT<<<wcg, 256>>>(wo, woh, wol);
    split_bf16<<<NELEM / 4 / 256, 256>>>(x, xhi, xlo, NELEM / 4);

    // projections
    dim3 gg(PD / 128, PM / 128);
    gemm_mma<<<gg, 256, GEMM_SMEM>>>(xhi, xlo, wqh, wql, q);
    gemm_mma<<<gg, 256, GEMM_SMEM>>>(xhi, xlo, wkh, wkl, k);
    gemm_mma<<<gg, 256, GEMM_SMEM>>>(xhi, xlo, wvh, wvl, v);

    // adapter projections
    adapter_part<<<dim3(PD / 256, 8), 256>>>(adapter, wk, adp);
    adapter_reduce<<<(PAL * PD + 255) / 256, 256>>>(adp, ak);
    adapter_part<<<dim3(PD / 256, 8), 256>>>(adapter, wv, adp);
    adapter_reduce<<<(PAL * PD + 255) / 256, 256>>>(adp, av);

    // RoPE
    const int ropeN = PB * PS * PH * 64;
    rope_k<<<ropeN / 256, 256>>>(q, cosT, sinT);
    rope_k<<<ropeN / 256, 256>>>(k, cosT, sinT);

    // fp16 operands for attention
    split_fp16<<<NELEM / 4 / 256, 256>>>(q, qh16, ql16, NELEM / 4);
    split_fp16<<<NELEM / 4 / 256, 256>>>(k, kh16, kl16, NELEM / 4);
    cvt_fp16<<<NELEM / 4 / 256, 256>>>(v, vh16, NELEM / 4);

    // gated adapter softmax weights
    adapter_scores<<<PM * PH / 8, 256>>>(q, ak, gate, aw);

    // flash attention (HMMA)
    flashmma<<<dim3(PS / 128, PH, PB), 256, FLASH2_SMEM>>>(
        qh16, ql16, kh16, kl16, vh16, aw, av, o);

    // output projection
    split_bf16<<<NELEM / 4 / 256, 256>>>(o, ohi, olo, NELEM / 4);
    gemm_mma<<<gg, 256, GEMM_SMEM>>>(ohi, olo, woh, wol, out);
}